// round 1
// baseline (speedup 1.0000x reference)
#include <cuda_runtime.h>

// Problem constants (fixed by the reference)
#define H   128
#define MH  256
#define NJ  2000
#define NM  50
#define NS  200
#define G   8

// Scratch (static __device__ — no allocations allowed)
__device__ float d_Pj[NJ * MH];    // job projections through aW1 rows [0,128)
__device__ float d_Pmc[NM * MH];   // machine projections through aW1 rows [128,256) + c_vec
__device__ float d_cvec[MH];       // setup/global/bias constant part of layer 1

// ---------------------------------------------------------------------------
// K1: aggregates, global_emb, critic MLP (scalar), c_vec. One block, 1024 thr.
// ---------------------------------------------------------------------------
__global__ void k1_prep(const float* __restrict__ job_emb,
                        const float* __restrict__ machine_emb,
                        const float* __restrict__ setup_emb,
                        const float* __restrict__ gf,
                        const float* __restrict__ Wg,  const float* __restrict__ bg,
                        const float* __restrict__ aW1, const float* __restrict__ ab1,
                        const float* __restrict__ cW1, const float* __restrict__ cb1,
                        const float* __restrict__ cW2, const float* __restrict__ cb2,
                        const float* __restrict__ cW3, const float* __restrict__ cb3,
                        float* __restrict__ out_value)
{
    __shared__ float red[8][128];
    __shared__ float s_state[4 * H];   // [job_agg | machine_agg | setup_agg | global_emb]
    __shared__ float s_h1[MH];
    __shared__ float s_h2[MH];

    const int tid = threadIdx.x;
    const int col = tid & 127;
    const int grp = tid >> 7;          // 0..7

    // --- job mean ---
    float s = 0.f;
    for (int r = grp; r < NJ; r += 8) s += job_emb[r * H + col];
    red[grp][col] = s; __syncthreads();
    if (grp == 0) { float t = 0.f;
        #pragma unroll
        for (int g = 0; g < 8; g++) t += red[g][col];
        s_state[col] = t * (1.0f / NJ);
    }
    __syncthreads();

    // --- machine mean ---
    s = 0.f;
    for (int r = grp; r < NM; r += 8) s += machine_emb[r * H + col];
    red[grp][col] = s; __syncthreads();
    if (grp == 0) { float t = 0.f;
        #pragma unroll
        for (int g = 0; g < 8; g++) t += red[g][col];
        s_state[H + col] = t * (1.0f / NM);
    }
    __syncthreads();

    // --- setup mean ---
    s = 0.f;
    for (int r = grp; r < NS; r += 8) s += setup_emb[r * H + col];
    red[grp][col] = s; __syncthreads();
    if (grp == 0) { float t = 0.f;
        #pragma unroll
        for (int g = 0; g < 8; g++) t += red[g][col];
        s_state[2 * H + col] = t * (1.0f / NS);
    }
    __syncthreads();

    // --- global_emb = relu(gf @ Wg + bg) ---
    if (tid < H) {
        float a = bg[tid];
        #pragma unroll
        for (int g = 0; g < G; g++) a += gf[g] * Wg[g * H + tid];
        s_state[3 * H + tid] = fmaxf(a, 0.f);
    }
    __syncthreads();

    // --- c_vec[n] = setup_agg @ aW1[256:384] + global_emb @ aW1[384:512] + ab1 ---
    if (tid < MH) {
        float a = ab1[tid];
        #pragma unroll 4
        for (int k = 0; k < H; k++) a += s_state[2 * H + k] * aW1[(2 * H + k) * MH + tid];
        #pragma unroll 4
        for (int k = 0; k < H; k++) a += s_state[3 * H + k] * aW1[(3 * H + k) * MH + tid];
        d_cvec[tid] = a;
    }

    // --- critic MLP on s_state ---
    if (tid < MH) {
        float a = cb1[tid];
        #pragma unroll 4
        for (int k = 0; k < 4 * H; k++) a += s_state[k] * cW1[k * MH + tid];
        s_h1[tid] = fmaxf(a, 0.f);
    }
    __syncthreads();
    if (tid < MH) {
        float a = cb2[tid];
        #pragma unroll 4
        for (int k = 0; k < MH; k++) a += s_h1[k] * cW2[k * MH + tid];
        s_h2[tid] = fmaxf(a, 0.f) * cW3[tid];
    }
    __syncthreads();
    if (tid == 0) {
        float a = cb3[0];
        for (int k = 0; k < MH; k++) a += s_h2[k];
        *out_value = a;
    }
}

// ---------------------------------------------------------------------------
// K2: Pj = job_emb @ aW1[0:128]; Pmc = machine_emb @ aW1[128:256] + c_vec.
// One block per row, 256 threads (one output column each).
// ---------------------------------------------------------------------------
__global__ void k2_proj(const float* __restrict__ job_emb,
                        const float* __restrict__ machine_emb,
                        const float* __restrict__ aW1)
{
    __shared__ float row[H];
    const int b = blockIdx.x;
    const int tid = threadIdx.x;   // 0..255

    const float* src;
    const float* W;
    float* dst;
    float a = 0.f;
    if (b < NJ) {
        src = job_emb + b * H;  W = aW1;          dst = d_Pj + b * MH;
    } else {
        int m = b - NJ;
        src = machine_emb + m * H;  W = aW1 + H * MH;  dst = d_Pmc + m * MH;
        a = d_cvec[tid];
    }
    if (tid < H) row[tid] = src[tid];
    __syncthreads();
    #pragma unroll 4
    for (int k = 0; k < H; k++) a += row[k] * W[k * MH + tid];
    dst[tid] = a;
}

// ---------------------------------------------------------------------------
// K3: main pair GEMM. Block = 256 threads computes C[64 jobs × 256] for one
// machine m:  C = relu(Pj_tile + Pmc[m]) @ aW2, then fused epilogue
// logit = sum_n relu(C+ab2)*aW3[n] + ab3.
// ---------------------------------------------------------------------------
#define BM 64
#define KT 16

__global__ __launch_bounds__(256, 2)
void k3_main(const float* __restrict__ aW2,
             const float* __restrict__ ab2,
             const float* __restrict__ aW3,
             const float* __restrict__ ab3,
             float* __restrict__ out)
{
    __shared__ float As[BM][KT + 1];       // H1 tile (relu applied)
    __shared__ float Bs[KT][MH + 4];       // aW2 tile
    __shared__ float s_b2[MH], s_w3[MH];

    const int tid = threadIdx.x;
    const int j0  = blockIdx.x * BM;
    const int m   = blockIdx.y;
    const int tr  = tid >> 4;   // 0..15 : row group
    const int tc  = tid & 15;   // 0..15 : col group (16 contiguous cols each)

    s_b2[tid] = ab2[tid];
    s_w3[tid] = aW3[tid];

    float acc[4][16];
    #pragma unroll
    for (int i = 0; i < 4; i++)
        #pragma unroll
        for (int c = 0; c < 16; c++) acc[i][c] = 0.f;

    const float* Pm = d_Pmc + m * MH;

    // A fill indices (constant over k-loop)
    const int ar  = tid >> 2;            // 0..63 : tile row
    const int ak4 = (tid & 3) * 4;       // 0,4,8,12
    const int aj  = j0 + ar;

    for (int k0 = 0; k0 < MH; k0 += KT) {
        __syncthreads();
        // ---- fill A tile: H1 = relu(Pj + Pmc) ----
        {
            float4 v;
            if (aj < NJ) {
                const float4 pj = *(const float4*)&d_Pj[aj * MH + k0 + ak4];
                const float4 pm = *(const float4*)&Pm[k0 + ak4];
                v.x = fmaxf(pj.x + pm.x, 0.f);
                v.y = fmaxf(pj.y + pm.y, 0.f);
                v.z = fmaxf(pj.z + pm.z, 0.f);
                v.w = fmaxf(pj.w + pm.w, 0.f);
            } else v = make_float4(0.f, 0.f, 0.f, 0.f);
            As[ar][ak4]     = v.x;
            As[ar][ak4 + 1] = v.y;
            As[ar][ak4 + 2] = v.z;
            As[ar][ak4 + 3] = v.w;
        }
        // ---- fill B tile: aW2[k0:k0+16, 0:256] ----
        #pragma unroll
        for (int u = 0; u < 4; u++) {
            int idx = tid + u * 256;       // float4 index 0..1023
            int kr  = idx >> 6;            // 0..15
            int cc  = (idx & 63) * 4;
            *(float4*)&Bs[kr][cc] = *(const float4*)&aW2[(k0 + kr) * MH + cc];
        }
        __syncthreads();
        // ---- compute ----
        #pragma unroll
        for (int kk = 0; kk < KT; kk++) {
            const float a0 = As[tr][kk];
            const float a1 = As[tr + 16][kk];
            const float a2 = As[tr + 32][kk];
            const float a3 = As[tr + 48][kk];
            float b[16];
            #pragma unroll
            for (int c4 = 0; c4 < 4; c4++) {
                float4 bv = *(const float4*)&Bs[kk][tc * 16 + c4 * 4];
                b[c4 * 4]     = bv.x;
                b[c4 * 4 + 1] = bv.y;
                b[c4 * 4 + 2] = bv.z;
                b[c4 * 4 + 3] = bv.w;
            }
            #pragma unroll
            for (int c = 0; c < 16; c++) {
                acc[0][c] += a0 * b[c];
                acc[1][c] += a1 * b[c];
                acc[2][c] += a2 * b[c];
                acc[3][c] += a3 * b[c];
            }
        }
    }

    // ---- fused epilogue: logit = sum_n relu(C + b2) * w3 + b3 ----
    const float bias3 = ab3[0];
    #pragma unroll
    for (int i = 0; i < 4; i++) {
        float p = 0.f;
        #pragma unroll
        for (int c = 0; c < 16; c++) {
            const int col = tc * 16 + c;
            p += fmaxf(acc[i][c] + s_b2[col], 0.f) * s_w3[col];
        }
        // reduce across the 16 tc lanes (contiguous within half-warp)
        #pragma unroll
        for (int off = 8; off; off >>= 1)
            p += __shfl_xor_sync(0xffffffffu, p, off, 16);
        const int j = j0 + tr + 16 * i;
        if (tc == 0 && j < NJ)
            out[j * NM + m] = p + bias3;
    }
}

// ---------------------------------------------------------------------------
extern "C" void kernel_launch(void* const* d_in, const int* in_sizes, int n_in,
                              void* d_out, int out_size)
{
    const float* job_emb     = (const float*)d_in[0];
    const float* machine_emb = (const float*)d_in[1];
    const float* setup_emb   = (const float*)d_in[2];
    const float* gf          = (const float*)d_in[3];
    const float* Wg          = (const float*)d_in[4];
    const float* bg          = (const float*)d_in[5];
    const float* aW1         = (const float*)d_in[6];
    const float* ab1         = (const float*)d_in[7];
    const float* aW2         = (const float*)d_in[8];
    const float* ab2         = (const float*)d_in[9];
    const float* aW3         = (const float*)d_in[10];
    const float* ab3         = (const float*)d_in[11];
    const float* cW1         = (const float*)d_in[12];
    const float* cb1         = (const float*)d_in[13];
    const float* cW2         = (const float*)d_in[14];
    const float* cb2         = (const float*)d_in[15];
    const float* cW3         = (const float*)d_in[16];
    const float* cb3         = (const float*)d_in[17];

    float* out = (float*)d_out;
    float* out_value = out + (out_size - 1);   // logits [NJ*NM], then scalar value

    k1_prep<<<1, 1024>>>(job_emb, machine_emb, setup_emb, gf, Wg, bg,
                         aW1, ab1, cW1, cb1, cW2, cb2, cW3, cb3, out_value);

    k2_proj<<<NJ + NM, MH>>>(job_emb, machine_emb, aW1);

    dim3 grid((NJ + BM - 1) / BM, NM);
    k3_main<<<grid, 256>>>(aW2, ab2, aW3, ab3, out);
}

// round 2
// speedup vs baseline: 2.6709x; 2.6709x over previous
#include <cuda_runtime.h>

#define H   128
#define MH  256
#define NJ  2000
#define NJP 2048           // padded jobs
#define NM  50
#define NS  200
#define G   8

// ---------------- device scratch (no allocations allowed) ----------------
__device__ float d_Pj[NJP * MH];     // job projections through aW1 rows [0,128)
__device__ float d_Pmc[NM * MH];     // machine proj through aW1 rows [128,256) + c_vec
__device__ float d_cvec[MH];         // setup/global/bias constant of layer 1
__device__ float d_state[4 * H];     // [job_agg | machine_agg | setup_agg | global_emb]
__device__ float d_ch1[MH];          // critic hidden 1 (relu applied)
__device__ float d_ch2[MH];          // relu(h2+b2)*w3
__device__ float d_partJ[32 * H];
__device__ float d_partM[H];
__device__ float d_partS[4 * H];

__device__ __forceinline__ float relu(float x) { return fmaxf(x, 0.f); }

// ---------------------------------------------------------------------------
// k1a: partial column sums of job/machine/setup embeddings. 37 blocks x 128.
//   bx in [0,32): job rows bx::32  -> d_partJ[bx]
//   bx == 32   : machine rows      -> d_partM
//   bx in [33,37): setup rows (bx-33)::4 -> d_partS[bx-33]
// ---------------------------------------------------------------------------
__global__ void k1a_partial(const float* __restrict__ job_emb,
                            const float* __restrict__ machine_emb,
                            const float* __restrict__ setup_emb)
{
    const int col = threadIdx.x;
    const int bx  = blockIdx.x;
    float s0 = 0.f, s1 = 0.f, s2 = 0.f, s3 = 0.f;

    if (bx < 32) {
        int r = bx;
        for (; r + 96 < NJ; r += 128) {
            s0 += job_emb[r * H + col];
            s1 += job_emb[(r + 32) * H + col];
            s2 += job_emb[(r + 64) * H + col];
            s3 += job_emb[(r + 96) * H + col];
        }
        for (; r < NJ; r += 32) s0 += job_emb[r * H + col];
        d_partJ[bx * H + col] = s0 + s1 + s2 + s3;
    } else if (bx == 32) {
        int r = 0;
        for (; r + 3 < NM; r += 4) {
            s0 += machine_emb[r * H + col];
            s1 += machine_emb[(r + 1) * H + col];
            s2 += machine_emb[(r + 2) * H + col];
            s3 += machine_emb[(r + 3) * H + col];
        }
        for (; r < NM; r++) s0 += machine_emb[r * H + col];
        d_partM[col] = s0 + s1 + s2 + s3;
    } else {
        const int sb = bx - 33;
        int r = sb;
        for (; r + 12 < NS; r += 16) {
            s0 += setup_emb[r * H + col];
            s1 += setup_emb[(r + 4) * H + col];
            s2 += setup_emb[(r + 8) * H + col];
            s3 += setup_emb[(r + 12) * H + col];
        }
        for (; r < NS; r += 4) s0 += setup_emb[r * H + col];
        d_partS[sb * H + col] = s0 + s1 + s2 + s3;
    }
}

// ---------------------------------------------------------------------------
// k1b: reduce partials into d_state, compute global_emb. 1 block x 128.
// ---------------------------------------------------------------------------
__global__ void k1b_state(const float* __restrict__ gf,
                          const float* __restrict__ Wg,
                          const float* __restrict__ bg)
{
    const int col = threadIdx.x;
    float t = 0.f;
    #pragma unroll
    for (int g = 0; g < 32; g++) t += d_partJ[g * H + col];
    d_state[col] = t * (1.0f / NJ);

    d_state[H + col] = d_partM[col] * (1.0f / NM);

    t = 0.f;
    #pragma unroll
    for (int g = 0; g < 4; g++) t += d_partS[g * H + col];
    d_state[2 * H + col] = t * (1.0f / NS);

    float a = bg[col];
    #pragma unroll
    for (int g = 0; g < G; g++) a += gf[g] * Wg[g * H + col];
    d_state[3 * H + col] = relu(a);
}

// ---------------------------------------------------------------------------
// k1c: c_vec (blocks 0..3) and critic h1 (blocks 4..11). 12 blocks x 256.
// ---------------------------------------------------------------------------
__global__ void k1c_cvec_ch1(const float* __restrict__ aW1,
                             const float* __restrict__ ab1,
                             const float* __restrict__ cW1,
                             const float* __restrict__ cb1)
{
    __shared__ float red[8][64];
    const int bx = blockIdx.x;
    const int tid = threadIdx.x;

    if (bx < 4) {
        // c_vec: 64 cols per block, K=256 (aW1 rows 256..511), 4-way split-K
        const int c = tid & 63, p = tid >> 6;
        const int col = bx * 64 + c;
        float s = 0.f;
        const int kb = p * 64;
        #pragma unroll 8
        for (int k = 0; k < 64; k++)
            s += d_state[2 * H + kb + k] * aW1[(2 * H + kb + k) * MH + col];
        red[p][c] = s;
        __syncthreads();
        if (p == 0)
            d_cvec[col] = ab1[col] + red[0][c] + red[1][c] + red[2][c] + red[3][c];
    } else {
        // critic h1: 32 cols per block, K=512, 8-way split-K
        const int q = bx - 4;
        const int c = tid & 31, p = tid >> 5;
        const int col = q * 32 + c;
        float s = 0.f;
        const int kb = p * 64;
        #pragma unroll 8
        for (int k = 0; k < 64; k++)
            s += d_state[kb + k] * cW1[(kb + k) * MH + col];
        red[p][c] = s;
        __syncthreads();
        if (p == 0) {
            float t = cb1[col];
            #pragma unroll
            for (int g = 0; g < 8; g++) t += red[g][c];
            d_ch1[col] = relu(t);
        }
    }
}

// ---------------------------------------------------------------------------
// k1d: critic layer2 * w3. 8 blocks x 256, 32 cols each, K=256, 8-way split-K.
// ---------------------------------------------------------------------------
__global__ void k1d_ch2(const float* __restrict__ cW2,
                        const float* __restrict__ cb2,
                        const float* __restrict__ cW3)
{
    __shared__ float red[8][32];
    const int tid = threadIdx.x;
    const int c = tid & 31, p = tid >> 5;
    const int col = blockIdx.x * 32 + c;
    float s = 0.f;
    const int kb = p * 32;
    #pragma unroll 8
    for (int k = 0; k < 32; k++)
        s += d_ch1[kb + k] * cW2[(kb + k) * MH + col];
    red[p][c] = s;
    __syncthreads();
    if (p == 0) {
        float t = cb2[col];
        #pragma unroll
        for (int g = 0; g < 8; g++) t += red[g][c];
        d_ch2[col] = relu(t) * cW3[col];
    }
}

// ---------------------------------------------------------------------------
// k1e: final critic reduction -> out_value. 1 block x 256.
// ---------------------------------------------------------------------------
__global__ void k1e_value(const float* __restrict__ cb3, float* __restrict__ out_value)
{
    __shared__ float red[256];
    const int tid = threadIdx.x;
    red[tid] = d_ch2[tid];
    __syncthreads();
    for (int off = 128; off; off >>= 1) {
        if (tid < off) red[tid] += red[tid + off];
        __syncthreads();
    }
    if (tid == 0) *out_value = red[0] + cb3[0];
}

// ---------------------------------------------------------------------------
// k2: projections. 132 blocks x 256.
//   bx < 128 : 16-job tile  -> d_Pj   (rows >= NJ written as zeros)
//   bx >= 128: 16-machine tile -> d_Pmc (+ c_vec), guarded m < NM
// ---------------------------------------------------------------------------
__global__ __launch_bounds__(256)
void k2_proj(const float* __restrict__ job_emb,
             const float* __restrict__ machine_emb,
             const float* __restrict__ aW1)
{
    __shared__ float s_src[16][H];
    const int bx = blockIdx.x;
    const int tid = threadIdx.x;
    const bool is_job = (bx < 128);
    const int r0 = is_job ? bx * 16 : (bx - 128) * 16;
    const int limit = is_job ? NJ : NM;
    const float* __restrict__ src = is_job ? job_emb : machine_emb;
    const float* __restrict__ W   = is_job ? aW1 : (aW1 + H * MH);

    for (int e = tid; e < 16 * H; e += 256) {
        const int j = e >> 7, k = e & 127;
        const int row = r0 + j;
        s_src[j][k] = (row < limit) ? src[row * H + k] : 0.f;
    }
    __syncthreads();

    const int col = tid;
    float acc[16];
    #pragma unroll
    for (int j = 0; j < 16; j++) acc[j] = 0.f;

    #pragma unroll 2
    for (int k = 0; k < H; k += 4) {
        float w0 = W[(k + 0) * MH + col];
        float w1 = W[(k + 1) * MH + col];
        float w2 = W[(k + 2) * MH + col];
        float w3 = W[(k + 3) * MH + col];
        #pragma unroll
        for (int j = 0; j < 16; j++) {
            const float4 s = *(const float4*)&s_src[j][k];
            acc[j] += s.x * w0 + s.y * w1 + s.z * w2 + s.w * w3;
        }
    }

    if (is_job) {
        #pragma unroll
        for (int j = 0; j < 16; j++)
            d_Pj[(r0 + j) * MH + col] = acc[j];          // zero rows included
    } else {
        const float cv = d_cvec[col];
        #pragma unroll
        for (int j = 0; j < 16; j++)
            if (r0 + j < NM) d_Pmc[(r0 + j) * MH + col] = acc[j] + cv;
    }
}

// ---------------------------------------------------------------------------
// k3: main pair GEMM + fused epilogue.
// Block: 256 threads (16x16), tile 128 jobs x 256 cols, K=256, KT=16.
// Thread micro-tile: 8 rows x 16 cols (cols strided tx*4 + u*64 -> bank-free).
// ---------------------------------------------------------------------------
#define BM 128
#define KT 16

__global__ __launch_bounds__(256, 1)
void k3_main(const float* __restrict__ aW2,
             const float* __restrict__ ab2,
             const float* __restrict__ aW3,
             const float* __restrict__ ab3,
             float* __restrict__ out)
{
    __shared__ float As[KT][BM];        // k-major activation tile (relu applied)
    __shared__ float Bs[KT][MH];        // aW2 tile
    __shared__ float s_b2[MH], s_w3[MH];

    const int tid = threadIdx.x;
    const int ty = tid >> 4;            // 0..15 -> rows ty*8 .. ty*8+7
    const int tx = tid & 15;            // 0..15 -> cols tx*4 + u*64 + v
    const int j0 = blockIdx.x * BM;
    const int m  = blockIdx.y;

    s_b2[tid] = ab2[tid];
    s_w3[tid] = aW3[tid];
    const float bias3 = ab3[0];

    float acc[8][16];
    #pragma unroll
    for (int i = 0; i < 8; i++)
        #pragma unroll
        for (int c = 0; c < 16; c++) acc[i][c] = 0.f;

    const float* __restrict__ Pm = d_Pmc + m * MH;
    const int arow = tid & 127;         // A-fill row
    const int aq0  = tid >> 7;          // 0 or 1 -> quads {aq0, aq0+2}

    for (int k0 = 0; k0 < MH; k0 += KT) {
        __syncthreads();
        // ---- fill A (transposed, relu(Pj + Pmc)) ----
        #pragma unroll
        for (int qi = 0; qi < 2; qi++) {
            const int q = aq0 + qi * 2;                 // 0..3
            const float4 pj = *(const float4*)&d_Pj[(j0 + arow) * MH + k0 + q * 4];
            const float4 pm = *(const float4*)&Pm[k0 + q * 4];
            As[q * 4 + 0][arow] = relu(pj.x + pm.x);
            As[q * 4 + 1][arow] = relu(pj.y + pm.y);
            As[q * 4 + 2][arow] = relu(pj.z + pm.z);
            As[q * 4 + 3][arow] = relu(pj.w + pm.w);
        }
        // ---- fill B: aW2[k0:k0+16, :] ----
        #pragma unroll
        for (int u = 0; u < 4; u++) {
            const int idx = tid + u * 256;              // float4 index 0..1023
            const int kr = idx >> 6;
            const int cc = (idx & 63) * 4;
            *(float4*)&Bs[kr][cc] = *(const float4*)&aW2[(k0 + kr) * MH + cc];
        }
        __syncthreads();
        // ---- compute ----
        #pragma unroll 8
        for (int kk = 0; kk < KT; kk++) {
            const float4 a0 = *(const float4*)&As[kk][ty * 8];
            const float4 a1 = *(const float4*)&As[kk][ty * 8 + 4];
            const float a[8] = {a0.x, a0.y, a0.z, a0.w, a1.x, a1.y, a1.z, a1.w};
            float b[16];
            #pragma unroll
            for (int u = 0; u < 4; u++) {
                const float4 bv = *(const float4*)&Bs[kk][tx * 4 + u * 64];
                b[u * 4 + 0] = bv.x; b[u * 4 + 1] = bv.y;
                b[u * 4 + 2] = bv.z; b[u * 4 + 3] = bv.w;
            }
            #pragma unroll
            for (int i = 0; i < 8; i++)
                #pragma unroll
                for (int c = 0; c < 16; c++)
                    acc[i][c] += a[i] * b[c];
        }
    }

    // ---- fused epilogue: logit = sum_n relu(C + b2)*w3 + b3 ----
    #pragma unroll
    for (int i = 0; i < 8; i++) {
        float p = 0.f;
        #pragma unroll
        for (int u = 0; u < 4; u++)
            #pragma unroll
            for (int v = 0; v < 4; v++) {
                const int col = tx * 4 + u * 64 + v;
                p += relu(acc[i][u * 4 + v] + s_b2[col]) * s_w3[col];
            }
        #pragma unroll
        for (int off = 8; off; off >>= 1)
            p += __shfl_xor_sync(0xffffffffu, p, off, 16);
        const int j = j0 + ty * 8 + i;
        if (tx == 0 && j < NJ)
            out[j * NM + m] = p + bias3;
    }
}

// ---------------------------------------------------------------------------
extern "C" void kernel_launch(void* const* d_in, const int* in_sizes, int n_in,
                              void* d_out, int out_size)
{
    const float* job_emb     = (const float*)d_in[0];
    const float* machine_emb = (const float*)d_in[1];
    const float* setup_emb   = (const float*)d_in[2];
    const float* gf          = (const float*)d_in[3];
    const float* Wg          = (const float*)d_in[4];
    const float* bg          = (const float*)d_in[5];
    const float* aW1         = (const float*)d_in[6];
    const float* ab1         = (const float*)d_in[7];
    const float* aW2         = (const float*)d_in[8];
    const float* ab2         = (const float*)d_in[9];
    const float* aW3         = (const float*)d_in[10];
    const float* ab3         = (const float*)d_in[11];
    const float* cW1         = (const float*)d_in[12];
    const float* cb1         = (const float*)d_in[13];
    const float* cW2         = (const float*)d_in[14];
    const float* cb2         = (const float*)d_in[15];
    const float* cW3         = (const float*)d_in[16];
    const float* cb3         = (const float*)d_in[17];

    float* out = (float*)d_out;
    float* out_value = out + (out_size - 1);

    k1a_partial<<<37, 128>>>(job_emb, machine_emb, setup_emb);
    k1b_state<<<1, 128>>>(gf, Wg, bg);
    k1c_cvec_ch1<<<12, 256>>>(aW1, ab1, cW1, cb1);
    k2_proj<<<132, 256>>>(job_emb, machine_emb, aW1);
    k1d_ch2<<<8, 256>>>(cW2, cb2, cW3);
    k1e_value<<<1, 256>>>(cb3, out_value);

    dim3 grid(NJP / BM, NM);
    k3_main<<<grid, 256>>>(aW2, ab2, aW3, ab3, out);
}

// round 4
// speedup vs baseline: 7.4256x; 2.7802x over previous
#include <cuda_runtime.h>
#include <cuda_fp16.h>
#include <cstdint>

#define H   128
#define MH  256
#define NJ  2000
#define NJP 2048
#define NM  50
#define NS  200
#define G   8

#define BSK   264                 // padded B row length in f16 (256 + 8)
#define BROWB 528                 // bytes per padded B row

// ---------------- device scratch ----------------
__device__ float d_Pj[NJP * MH];          // job projections (rows >= NJ stay zero)
__device__ float d_Pmc[NM * MH];          // machine proj + c_vec
__device__ float d_cvec[MH];
__device__ float d_state[4 * H];
__device__ float d_ch1[MH];
__device__ float d_ch2[MH];
__device__ float d_partJ[32 * H];
__device__ float d_partM[H];
__device__ float d_partS[4 * H];
__device__ __half d_Bt16[MH * BSK];       // aW2 transposed [n][k], fp16, padded rows

__device__ __forceinline__ float relu(float x) { return fmaxf(x, 0.f); }

// ---------------------------------------------------------------------------
// k1a: partial column sums. 37 blocks x 128.
// ---------------------------------------------------------------------------
__global__ void k1a_partial(const float* __restrict__ job_emb,
                            const float* __restrict__ machine_emb,
                            const float* __restrict__ setup_emb)
{
    const int col = threadIdx.x;
    const int bx  = blockIdx.x;
    float s0 = 0.f, s1 = 0.f, s2 = 0.f, s3 = 0.f;
    if (bx < 32) {
        int r = bx;
        for (; r + 96 < NJ; r += 128) {
            s0 += job_emb[r * H + col];
            s1 += job_emb[(r + 32) * H + col];
            s2 += job_emb[(r + 64) * H + col];
            s3 += job_emb[(r + 96) * H + col];
        }
        for (; r < NJ; r += 32) s0 += job_emb[r * H + col];
        d_partJ[bx * H + col] = s0 + s1 + s2 + s3;
    } else if (bx == 32) {
        int r = 0;
        for (; r + 3 < NM; r += 4) {
            s0 += machine_emb[r * H + col];
            s1 += machine_emb[(r + 1) * H + col];
            s2 += machine_emb[(r + 2) * H + col];
            s3 += machine_emb[(r + 3) * H + col];
        }
        for (; r < NM; r++) s0 += machine_emb[r * H + col];
        d_partM[col] = s0 + s1 + s2 + s3;
    } else {
        const int sb = bx - 33;
        int r = sb;
        for (; r + 12 < NS; r += 16) {
            s0 += setup_emb[r * H + col];
            s1 += setup_emb[(r + 4) * H + col];
            s2 += setup_emb[(r + 8) * H + col];
            s3 += setup_emb[(r + 12) * H + col];
        }
        for (; r < NS; r += 4) s0 += setup_emb[r * H + col];
        d_partS[sb * H + col] = s0 + s1 + s2 + s3;
    }
}

// ---------------------------------------------------------------------------
// k1b: reduce partials, global_emb. 1 block x 128.
// ---------------------------------------------------------------------------
__global__ void k1b_state(const float* __restrict__ gf,
                          const float* __restrict__ Wg,
                          const float* __restrict__ bg)
{
    const int col = threadIdx.x;
    float t = 0.f;
    #pragma unroll
    for (int g = 0; g < 32; g++) t += d_partJ[g * H + col];
    d_state[col] = t * (1.0f / NJ);
    d_state[H + col] = d_partM[col] * (1.0f / NM);
    t = 0.f;
    #pragma unroll
    for (int g = 0; g < 4; g++) t += d_partS[g * H + col];
    d_state[2 * H + col] = t * (1.0f / NS);
    float a = bg[col];
    #pragma unroll
    for (int g = 0; g < G; g++) a += gf[g] * Wg[g * H + col];
    d_state[3 * H + col] = relu(a);
}

// ---------------------------------------------------------------------------
// k1c: c_vec (blocks 0..3) + critic h1 (blocks 4..11). 12 blocks x 256.
// ---------------------------------------------------------------------------
__global__ void k1c_cvec_ch1(const float* __restrict__ aW1,
                             const float* __restrict__ ab1,
                             const float* __restrict__ cW1,
                             const float* __restrict__ cb1)
{
    __shared__ float red[8][64];
    const int bx = blockIdx.x;
    const int tid = threadIdx.x;
    if (bx < 4) {
        const int c = tid & 63, p = tid >> 6;
        const int col = bx * 64 + c;
        float s = 0.f;
        const int kb = p * 64;
        #pragma unroll 8
        for (int k = 0; k < 64; k++)
            s += d_state[2 * H + kb + k] * aW1[(2 * H + kb + k) * MH + col];
        red[p][c] = s;
        __syncthreads();
        if (p == 0)
            d_cvec[col] = ab1[col] + red[0][c] + red[1][c] + red[2][c] + red[3][c];
    } else {
        const int q = bx - 4;
        const int c = tid & 31, p = tid >> 5;
        const int col = q * 32 + c;
        float s = 0.f;
        const int kb = p * 64;
        #pragma unroll 8
        for (int k = 0; k < 64; k++)
            s += d_state[kb + k] * cW1[(kb + k) * MH + col];
        red[p][c] = s;
        __syncthreads();
        if (p == 0) {
            float t = cb1[col];
            #pragma unroll
            for (int g = 0; g < 8; g++) t += red[g][c];
            d_ch1[col] = relu(t);
        }
    }
}

// ---------------------------------------------------------------------------
// k1d: critic layer2 * w3. 8 blocks x 256.
// ---------------------------------------------------------------------------
__global__ void k1d_ch2(const float* __restrict__ cW2,
                        const float* __restrict__ cb2,
                        const float* __restrict__ cW3)
{
    __shared__ float red[8][32];
    const int tid = threadIdx.x;
    const int c = tid & 31, p = tid >> 5;
    const int col = blockIdx.x * 32 + c;
    float s = 0.f;
    const int kb = p * 32;
    #pragma unroll 8
    for (int k = 0; k < 32; k++)
        s += d_ch1[kb + k] * cW2[(kb + k) * MH + col];
    red[p][c] = s;
    __syncthreads();
    if (p == 0) {
        float t = cb2[col];
        #pragma unroll
        for (int g = 0; g < 8; g++) t += red[g][c];
        d_ch2[col] = relu(t) * cW3[col];
    }
}

// ---------------------------------------------------------------------------
// k1e: final critic reduction. 1 block x 256.
// ---------------------------------------------------------------------------
__global__ void k1e_value(const float* __restrict__ cb3, float* __restrict__ out_value)
{
    __shared__ float red[256];
    const int tid = threadIdx.x;
    red[tid] = d_ch2[tid];
    __syncthreads();
    for (int off = 128; off; off >>= 1) {
        if (tid < off) red[tid] += red[tid + off];
        __syncthreads();
    }
    if (tid == 0) *out_value = red[0] + cb3[0];
}

// ---------------------------------------------------------------------------
// k2b: transpose aW2 -> d_Bt16 [n][k] fp16, padded rows. grid (8,8), 32x32.
// ---------------------------------------------------------------------------
__global__ void k2b_prepB(const float* __restrict__ aW2)
{
    __shared__ float t[32][33];
    const int tx = threadIdx.x, ty = threadIdx.y;
    const int k0 = blockIdx.y * 32, n0 = blockIdx.x * 32;
    t[ty][tx] = aW2[(k0 + ty) * MH + n0 + tx];
    __syncthreads();
    d_Bt16[(n0 + ty) * BSK + k0 + tx] = __float2half_rn(t[tx][ty]);
}

// ---------------------------------------------------------------------------
// k2: projections, 4-row tiles. 513 blocks x 256.
// ---------------------------------------------------------------------------
__global__ __launch_bounds__(256)
void k2_proj(const float* __restrict__ job_emb,
             const float* __restrict__ machine_emb,
             const float* __restrict__ aW1)
{
    __shared__ float s_src[4][H];
    const int bx = blockIdx.x;
    const int tid = threadIdx.x;
    const bool is_job = (bx < 500);
    const int r0 = is_job ? bx * 4 : (bx - 500) * 4;
    const int limit = is_job ? NJ : NM;
    const float* __restrict__ src = is_job ? job_emb : machine_emb;
    const float* __restrict__ W   = is_job ? aW1 : (aW1 + H * MH);

    for (int e = tid; e < 4 * H; e += 256) {
        const int j = e >> 7, k = e & 127;
        const int r = r0 + j;
        s_src[j][k] = (r < limit) ? src[r * H + k] : 0.f;
    }
    __syncthreads();

    const int col = tid;
    float a0 = 0.f, a1 = 0.f, a2 = 0.f, a3 = 0.f;
    #pragma unroll 8
    for (int k = 0; k < H; k++) {
        const float w = W[k * MH + col];
        a0 += s_src[0][k] * w;
        a1 += s_src[1][k] * w;
        a2 += s_src[2][k] * w;
        a3 += s_src[3][k] * w;
    }
    if (is_job) {
        d_Pj[(r0 + 0) * MH + col] = a0;
        d_Pj[(r0 + 1) * MH + col] = a1;
        d_Pj[(r0 + 2) * MH + col] = a2;
        d_Pj[(r0 + 3) * MH + col] = a3;
    } else {
        const float cv = d_cvec[col];
        if (r0 + 0 < NM) d_Pmc[(r0 + 0) * MH + col] = a0 + cv;
        if (r0 + 1 < NM) d_Pmc[(r0 + 1) * MH + col] = a1 + cv;
        if (r0 + 2 < NM) d_Pmc[(r0 + 2) * MH + col] = a2 + cv;
        if (r0 + 3 < NM) d_Pmc[(r0 + 3) * MH + col] = a3 + cv;
    }
}

// ---------------------------------------------------------------------------
// k3: mma.sync fp16 GEMM + fused epilogue.
// Block 512 thr (16 warps, 4m x 4n). Tile: 128 jobs x 256 cols, K=256.
// A frags built in registers from fp32 Pj+Pm (relu), B^T fp16 smem-resident.
// ---------------------------------------------------------------------------
#define OFF_B   0
#define OFF_PM  (MH * BROWB)                 // 135168
#define OFF_B2  (OFF_PM + 1024)
#define OFF_W3  (OFF_B2 + 1024)
#define OFF_RED (OFF_W3 + 1024)
#define K3_SMEM (OFF_RED + 128 * 4 * 4)      // 140288

__device__ __forceinline__ uint32_t packh2(float x, float y) {
    __half2 h = __floats2half2_rn(x, y);     // x -> low, y -> high
    return *(uint32_t*)&h;
}

__global__ __launch_bounds__(512, 1)
void k3_mma(const float* __restrict__ ab2,
            const float* __restrict__ aW3,
            const float* __restrict__ ab3,
            float* __restrict__ out)
{
    extern __shared__ char smem[];
    float* s_pm  = (float*)(smem + OFF_PM);
    float* s_b2  = (float*)(smem + OFF_B2);
    float* s_w3  = (float*)(smem + OFF_W3);
    float* s_red = (float*)(smem + OFF_RED);

    const int tid  = threadIdx.x;
    const int lane = tid & 31;
    const int warp = tid >> 5;
    const int wm   = warp >> 2;     // 0..3
    const int wn   = warp & 3;      // 0..3
    const int j0   = blockIdx.x * 128;
    const int m    = blockIdx.y;

    // ---- fill B^T smem (135168 B = 8448 uint4; padded layout matches gmem) ----
    {
        const uint4* bsrc = (const uint4*)d_Bt16;
        uint4* bdst = (uint4*)(smem + OFF_B);
        #pragma unroll
        for (int i = 0; i < 17; i++) {
            const int idx = tid + i * 512;
            if (idx < (MH * BROWB) / 16) bdst[idx] = bsrc[idx];
        }
    }
    if (tid < MH) {
        s_pm[tid] = d_Pmc[m * MH + tid];
        s_b2[tid] = ab2[tid];
        s_w3[tid] = aW3[tid];
    }
    __syncthreads();

    float acc[2][8][4];
    #pragma unroll
    for (int mt = 0; mt < 2; mt++)
        #pragma unroll
        for (int nt = 0; nt < 8; nt++)
            #pragma unroll
            for (int c = 0; c < 4; c++) acc[mt][nt][c] = 0.f;

    const int r4 = lane >> 2;            // 0..7
    const int kq = (lane & 3) * 2;       // 0,2,4,6
    const int rowA = j0 + wm * 32 + r4;  // base row for this lane

    #pragma unroll 4
    for (int ks = 0; ks < 16; ks++) {
        const int k0 = ks * 16;
        const float2 pmA = *(const float2*)(s_pm + k0 + kq);
        const float2 pmB = *(const float2*)(s_pm + k0 + kq + 8);

        uint32_t a[2][4];
        #pragma unroll
        for (int mt = 0; mt < 2; mt++) {
            const float* base = d_Pj + (size_t)(rowA + mt * 16) * MH;
            const float2 p00 = *(const float2*)(base + k0 + kq);
            const float2 p10 = *(const float2*)(base + 8 * MH + k0 + kq);
            const float2 p01 = *(const float2*)(base + k0 + kq + 8);
            const float2 p11 = *(const float2*)(base + 8 * MH + k0 + kq + 8);
            a[mt][0] = packh2(relu(p00.x + pmA.x), relu(p00.y + pmA.y));
            a[mt][1] = packh2(relu(p10.x + pmA.x), relu(p10.y + pmA.y));
            a[mt][2] = packh2(relu(p01.x + pmB.x), relu(p01.y + pmB.y));
            a[mt][3] = packh2(relu(p11.x + pmB.x), relu(p11.y + pmB.y));
        }

        #pragma unroll
        for (int nt = 0; nt < 8; nt++) {
            const int n = wn * 64 + nt * 8 + r4;
            const char* brow = smem + OFF_B + n * BROWB;
            const uint32_t b0 = *(const uint32_t*)(brow + (k0 + kq) * 2);
            const uint32_t b1 = *(const uint32_t*)(brow + (k0 + kq + 8) * 2);
            asm volatile(
                "mma.sync.aligned.m16n8k16.row.col.f32.f16.f16.f32 "
                "{%0,%1,%2,%3}, {%4,%5,%6,%7}, {%8,%9}, {%0,%1,%2,%3};"
                : "+f"(acc[0][nt][0]), "+f"(acc[0][nt][1]),
                  "+f"(acc[0][nt][2]), "+f"(acc[0][nt][3])
                : "r"(a[0][0]), "r"(a[0][1]), "r"(a[0][2]), "r"(a[0][3]),
                  "r"(b0), "r"(b1));
            asm volatile(
                "mma.sync.aligned.m16n8k16.row.col.f32.f16.f16.f32 "
                "{%0,%1,%2,%3}, {%4,%5,%6,%7}, {%8,%9}, {%0,%1,%2,%3};"
                : "+f"(acc[1][nt][0]), "+f"(acc[1][nt][1]),
                  "+f"(acc[1][nt][2]), "+f"(acc[1][nt][3])
                : "r"(a[1][0]), "r"(a[1][1]), "r"(a[1][2]), "r"(a[1][3]),
                  "r"(b0), "r"(b1));
        }
    }

    // ---- fused epilogue: per-row logit = sum_col relu(c+b2)*w3 ----
    float part[2][2];        // [mt][row-group g: +0 / +8]
    part[0][0] = part[0][1] = part[1][0] = part[1][1] = 0.f;
    #pragma unroll
    for (int nt = 0; nt < 8; nt++) {
        const int col0 = wn * 64 + nt * 8 + kq;   // c0/c2 col
        const float b2a = s_b2[col0],     w3a = s_w3[col0];
        const float b2b = s_b2[col0 + 1], w3b = s_w3[col0 + 1];
        #pragma unroll
        for (int mt = 0; mt < 2; mt++) {
            part[mt][0] += relu(acc[mt][nt][0] + b2a) * w3a
                         + relu(acc[mt][nt][1] + b2b) * w3b;
            part[mt][1] += relu(acc[mt][nt][2] + b2a) * w3a
                         + relu(acc[mt][nt][3] + b2b) * w3b;
        }
    }
    // reduce over the 4 lanes sharing a row (lane^1, lane^2 keep same l>>2)
    #pragma unroll
    for (int mt = 0; mt < 2; mt++)
        #pragma unroll
        for (int g = 0; g < 2; g++) {
            part[mt][g] += __shfl_xor_sync(0xffffffffu, part[mt][g], 1);
            part[mt][g] += __shfl_xor_sync(0xffffffffu, part[mt][g], 2);
        }
    if ((lane & 3) == 0) {
        #pragma unroll
        for (int mt = 0; mt < 2; mt++)
            #pragma unroll
            for (int g = 0; g < 2; g++) {
                const int rl = wm * 32 + mt * 16 + g * 8 + r4;   // 0..127
                s_red[rl * 4 + wn] = part[mt][g];
            }
    }
    __syncthreads();
    if (tid < 128) {
        const int j = j0 + tid;
        if (j < NJ) {
            const float v = s_red[tid * 4 + 0] + s_red[tid * 4 + 1]
                          + s_red[tid * 4 + 2] + s_red[tid * 4 + 3] + ab3[0];
            out[j * NM + m] = v;
        }
    }
}

// ---------------------------------------------------------------------------
extern "C" void kernel_launch(void* const* d_in, const int* in_sizes, int n_in,
                              void* d_out, int out_size)
{
    const float* job_emb     = (const float*)d_in[0];
    const float* machine_emb = (const float*)d_in[1];
    const float* setup_emb   = (const float*)d_in[2];
    const float* gf          = (const float*)d_in[3];
    const float* Wg          = (const float*)d_in[4];
    const float* bg          = (const float*)d_in[5];
    const float* aW1         = (const float*)d_in[6];
    const float* ab1         = (const float*)d_in[7];
    const float* aW2         = (const float*)d_in[8];
    const float* ab2         = (const float*)d_in[9];
    const float* aW3         = (const float*)d_in[10];
    const float* ab3         = (const float*)d_in[11];
    const float* cW1         = (const float*)d_in[12];
    const float* cb1         = (const float*)d_in[13];
    const float* cW2         = (const float*)d_in[14];
    const float* cb2         = (const float*)d_in[15];
    const float* cW3         = (const float*)d_in[16];
    const float* cb3         = (const float*)d_in[17];

    float* out = (float*)d_out;
    float* out_value = out + (out_size - 1);

    cudaFuncSetAttribute(k3_mma, cudaFuncAttributeMaxDynamicSharedMemorySize, K3_SMEM);

    k2b_prepB<<<dim3(8, 8), dim3(32, 32)>>>(aW2);
    k1a_partial<<<37, 128>>>(job_emb, machine_emb, setup_emb);
    k1b_state<<<1, 128>>>(gf, Wg, bg);
    k1c_cvec_ch1<<<12, 256>>>(aW1, ab1, cW1, cb1);
    k2_proj<<<513, 256>>>(job_emb, machine_emb, aW1);
    k1d_ch2<<<8, 256>>>(cW2, cb2, cW3);
    k1e_value<<<1, 256>>>(cb3, out_value);

    dim3 grid(NJP / 128, NM);
    k3_mma<<<grid, 512, K3_SMEM>>>(ab2, aW3, ab3, out);
}

// round 5
// speedup vs baseline: 9.6989x; 1.3062x over previous
#include <cuda_runtime.h>
#include <cuda_fp16.h>
#include <cstdint>

#define H   128
#define MH  256
#define NJ  2000
#define NJP 2048
#define NM  50
#define NS  200
#define G   8

#define PADK  264                 // padded row length (halves)
#define ROWB  528                 // bytes per padded row

// ---------------- device scratch ----------------
__device__ __half d_Pj16[NJP * PADK];   // relu-input job projections, fp16 (pad rows zero)
__device__ __half d_Pm16[NM * PADK];    // machine proj + cvec, fp16
__device__ __half d_B16[MH * PADK];     // aW2^T [n][k] fp16
__device__ float  d_cvec[MH];
__device__ float  d_partJ[32 * H];
__device__ float  d_partM[H];
__device__ float  d_partS[4 * H];

__device__ __forceinline__ float relu(float x) { return fmaxf(x, 0.f); }

// ===========================================================================
// k_pre: 601 blocks x 256 threads.
//   bx <  500 : job projection (4 rows)  -> d_Pj16
//   500..563  : aW2 transpose 32x32 tile -> d_B16
//   564..600  : partial column sums      -> d_partJ / d_partM / d_partS
// ===========================================================================
__global__ __launch_bounds__(256)
void k_pre(const float* __restrict__ job_emb,
           const float* __restrict__ machine_emb,
           const float* __restrict__ setup_emb,
           const float* __restrict__ aW1,
           const float* __restrict__ aW2)
{
    __shared__ float buf[32 * 33];           // union: jobs use [4][128], transpose [32][33]
    const int bx = blockIdx.x;
    const int tid = threadIdx.x;

    if (bx < 500) {
        // ---- job projection, 4 rows ----
        float (*s_src)[H] = (float(*)[H])buf;
        const int r0 = bx * 4;
        for (int e = tid; e < 4 * H; e += 256) {
            const int j = e >> 7, k = e & 127;
            s_src[j][k] = job_emb[(r0 + j) * H + k];   // r0+3 <= 1999 < NJ always
        }
        __syncthreads();
        const int col = tid;
        float a0 = 0.f, a1 = 0.f, a2 = 0.f, a3 = 0.f;
        #pragma unroll 8
        for (int k = 0; k < H; k++) {
            const float w = aW1[k * MH + col];
            a0 += s_src[0][k] * w;
            a1 += s_src[1][k] * w;
            a2 += s_src[2][k] * w;
            a3 += s_src[3][k] * w;
        }
        d_Pj16[(r0 + 0) * PADK + col] = __float2half_rn(a0);
        d_Pj16[(r0 + 1) * PADK + col] = __float2half_rn(a1);
        d_Pj16[(r0 + 2) * PADK + col] = __float2half_rn(a2);
        d_Pj16[(r0 + 3) * PADK + col] = __float2half_rn(a3);
    } else if (bx < 564) {
        // ---- transpose aW2 [k][n] -> d_B16 [n][k] fp16 ----
        float (*tt)[33] = (float(*)[33])buf;
        const int t = bx - 500;
        const int k0 = (t >> 3) * 32, n0 = (t & 7) * 32;
        const int r = tid >> 5, c = tid & 31;
        #pragma unroll
        for (int i = 0; i < 4; i++)
            tt[r + i * 8][c] = aW2[(k0 + r + i * 8) * MH + n0 + c];
        __syncthreads();
        #pragma unroll
        for (int i = 0; i < 4; i++)
            d_B16[(n0 + r + i * 8) * PADK + k0 + c] = __float2half_rn(tt[c][r + i * 8]);
    } else {
        // ---- partial column sums (only threads 0..127 active) ----
        if (tid >= 128) return;
        const int col = tid;
        const int pb = bx - 564;                 // 0..36
        float s0 = 0.f, s1 = 0.f, s2 = 0.f, s3 = 0.f;
        if (pb < 32) {
            int r = pb;
            for (; r + 96 < NJ; r += 128) {
                s0 += job_emb[r * H + col];
                s1 += job_emb[(r + 32) * H + col];
                s2 += job_emb[(r + 64) * H + col];
                s3 += job_emb[(r + 96) * H + col];
            }
            for (; r < NJ; r += 32) s0 += job_emb[r * H + col];
            d_partJ[pb * H + col] = s0 + s1 + s2 + s3;
        } else if (pb == 32) {
            int r = 0;
            for (; r + 3 < NM; r += 4) {
                s0 += machine_emb[r * H + col];
                s1 += machine_emb[(r + 1) * H + col];
                s2 += machine_emb[(r + 2) * H + col];
                s3 += machine_emb[(r + 3) * H + col];
            }
            for (; r < NM; r++) s0 += machine_emb[r * H + col];
            d_partM[col] = s0 + s1 + s2 + s3;
        } else {
            const int sb = pb - 33;
            int r = sb;
            for (; r + 12 < NS; r += 16) {
                s0 += setup_emb[r * H + col];
                s1 += setup_emb[(r + 4) * H + col];
                s2 += setup_emb[(r + 8) * H + col];
                s3 += setup_emb[(r + 12) * H + col];
            }
            for (; r < NS; r += 4) s0 += setup_emb[r * H + col];
            d_partS[sb * H + col] = s0 + s1 + s2 + s3;
        }
    }
}

// ===========================================================================
// k_cvec: 8 blocks x 256. Recomputes setup_agg + global_emb from partials,
// then c_vec[col] (32 cols/block, 8-way split-K over K=256).
// ===========================================================================
__global__ __launch_bounds__(256)
void k_cvec(const float* __restrict__ gf,
            const float* __restrict__ Wg,
            const float* __restrict__ bg,
            const float* __restrict__ aW1,
            const float* __restrict__ ab1)
{
    __shared__ float s_sa[128], s_ge[128], red[8][32];
    const int tid = threadIdx.x;
    if (tid < 128) {
        s_sa[tid] = (d_partS[tid] + d_partS[128 + tid] + d_partS[256 + tid]
                     + d_partS[384 + tid]) * (1.0f / NS);
    } else {
        const int c = tid - 128;
        float a = bg[c];
        #pragma unroll
        for (int g = 0; g < G; g++) a += gf[g] * Wg[g * H + c];
        s_ge[c] = relu(a);
    }
    __syncthreads();

    const int c = tid & 31, p = tid >> 5;
    const int col = blockIdx.x * 32 + c;
    float s = 0.f;
    const int kb = p * 32;
    if (kb < 128) {
        #pragma unroll 8
        for (int k = 0; k < 32; k++)
            s += s_sa[kb + k] * aW1[(2 * H + kb + k) * MH + col];
    } else {
        #pragma unroll 8
        for (int k = 0; k < 32; k++)
            s += s_ge[kb - 128 + k] * aW1[(3 * H + kb - 128 + k) * MH + col];
    }
    red[p][c] = s;
    __syncthreads();
    if (p == 0) {
        float t = ab1[col];
        #pragma unroll
        for (int g = 0; g < 8; g++) t += red[g][c];
        d_cvec[col] = t;
    }
}

// ===========================================================================
// k_mach: 13 blocks x 256. Machine projections + cvec -> d_Pm16 fp16.
// ===========================================================================
__global__ __launch_bounds__(256)
void k_mach(const float* __restrict__ machine_emb,
            const float* __restrict__ aW1)
{
    __shared__ float s_src[4][H];
    const int r0 = blockIdx.x * 4;
    const int tid = threadIdx.x;
    for (int e = tid; e < 4 * H; e += 256) {
        const int j = e >> 7, k = e & 127;
        const int r = r0 + j;
        s_src[j][k] = (r < NM) ? machine_emb[r * H + k] : 0.f;
    }
    __syncthreads();
    const int col = tid;
    const float* __restrict__ W = aW1 + H * MH;
    float a0 = 0.f, a1 = 0.f, a2 = 0.f, a3 = 0.f;
    #pragma unroll 8
    for (int k = 0; k < H; k++) {
        const float w = W[k * MH + col];
        a0 += s_src[0][k] * w;
        a1 += s_src[1][k] * w;
        a2 += s_src[2][k] * w;
        a3 += s_src[3][k] * w;
    }
    const float cv = d_cvec[col];
    if (r0 + 0 < NM) d_Pm16[(r0 + 0) * PADK + col] = __float2half_rn(a0 + cv);
    if (r0 + 1 < NM) d_Pm16[(r0 + 1) * PADK + col] = __float2half_rn(a1 + cv);
    if (r0 + 2 < NM) d_Pm16[(r0 + 2) * PADK + col] = __float2half_rn(a2 + cv);
    if (r0 + 3 < NM) d_Pm16[(r0 + 3) * PADK + col] = __float2half_rn(a3 + cv);
}

// ===========================================================================
// k3: blocks 0..159 = GEMM (128 jobs x 5 machines), block 160 = critic.
// 512 threads. B + Pj tiles smem-resident fp16; A frags via ldmatrix+HADD2.
// ===========================================================================
#define OFF_B   0
#define OFF_PJ  135168
#define OFF_PM  202752
#define OFF_B2  205392
#define OFF_W3  206416
#define OFF_RED 207440
#define K3_SMEM 209488

__device__ __forceinline__ uint32_t smem_u32(const void* p) {
    uint32_t a;
    asm("{ .reg .u64 t; cvta.to.shared.u64 t, %1; cvt.u32.u64 %0, t; }" : "=r"(a) : "l"(p));
    return a;
}
__device__ __forceinline__ void ldm_x4(uint32_t& r0, uint32_t& r1, uint32_t& r2,
                                       uint32_t& r3, uint32_t addr) {
    asm volatile("ldmatrix.sync.aligned.m8n8.x4.shared.b16 {%0,%1,%2,%3}, [%4];"
                 : "=r"(r0), "=r"(r1), "=r"(r2), "=r"(r3) : "r"(addr));
}
__device__ __forceinline__ uint32_t addrelu2(uint32_t a, uint32_t pm) {
    const __half2 z = __float2half2_rn(0.f);
    __half2 x = __hadd2(*(__half2*)&a, *(__half2*)&pm);
    x = __hmax2(x, z);
    return *(uint32_t*)&x;
}
#define HMMA(acc, A0, A1, A2, A3, B0, B1)                                   \
    asm volatile(                                                            \
        "mma.sync.aligned.m16n8k16.row.col.f32.f16.f16.f32 "                \
        "{%0,%1,%2,%3}, {%4,%5,%6,%7}, {%8,%9}, {%0,%1,%2,%3};"             \
        : "+f"(acc[0]), "+f"(acc[1]), "+f"(acc[2]), "+f"(acc[3])            \
        : "r"(A0), "r"(A1), "r"(A2), "r"(A3), "r"(B0), "r"(B1))

__global__ __launch_bounds__(512, 1)
void k3_mma(const float* __restrict__ ab2,
            const float* __restrict__ aW3,
            const float* __restrict__ ab3,
            const float* __restrict__ gf,
            const float* __restrict__ Wg,
            const float* __restrict__ bg,
            const float* __restrict__ cW1, const float* __restrict__ cb1,
            const float* __restrict__ cW2, const float* __restrict__ cb2,
            const float* __restrict__ cW3, const float* __restrict__ cb3,
            float* __restrict__ out, float* __restrict__ out_value)
{
    extern __shared__ char smem[];
    const int tid  = threadIdx.x;
    const int lane = tid & 31;
    const int warp = tid >> 5;

    // ------------------------- critic block -------------------------------
    if (blockIdx.x == 160) {
        float* cs = (float*)smem;           // [0,512): state, [512,768): h1, [768,1024): h2
        if (tid < 128) {
            float t = 0.f;
            #pragma unroll
            for (int g = 0; g < 32; g++) t += d_partJ[g * H + tid];
            cs[tid] = t * (1.0f / NJ);
            cs[H + tid] = d_partM[tid] * (1.0f / NM);
            cs[2 * H + tid] = (d_partS[tid] + d_partS[128 + tid] + d_partS[256 + tid]
                               + d_partS[384 + tid]) * (1.0f / NS);
            float a = bg[tid];
            #pragma unroll
            for (int g = 0; g < G; g++) a += gf[g] * Wg[g * H + tid];
            cs[3 * H + tid] = relu(a);
        }
        __syncthreads();
        // h1: col = tid>>1, half = tid&1 over K=512
        {
            const int col = tid >> 1, half = tid & 1;
            float s = 0.f;
            const int kb = half * 256;
            #pragma unroll 16
            for (int k = 0; k < 256; k++)
                s += cs[kb + k] * cW1[(kb + k) * MH + col];
            s += __shfl_xor_sync(0xffffffffu, s, 1);
            __syncthreads();
            if (half == 0) cs[512 + col] = relu(s + cb1[col]);
        }
        __syncthreads();
        // h2
        {
            const int col = tid >> 1, half = tid & 1;
            float s = 0.f;
            const int kb = half * 128;
            #pragma unroll 16
            for (int k = 0; k < 128; k++)
                s += cs[512 + kb + k] * cW2[(kb + k) * MH + col];
            s += __shfl_xor_sync(0xffffffffu, s, 1);
            __syncthreads();
            if (half == 0) cs[768 + col] = relu(s + cb2[col]) * cW3[col];
        }
        __syncthreads();
        // reduce 256 -> value
        {
            float v = (tid < 256) ? cs[768 + tid] : 0.f;
            #pragma unroll
            for (int off = 16; off; off >>= 1) v += __shfl_xor_sync(0xffffffffu, v, off);
            __syncthreads();
            if (lane == 0) cs[warp] = v;
            __syncthreads();
            if (tid == 0) {
                float t = cb3[0];
                #pragma unroll
                for (int w = 0; w < 16; w++) t += cs[w];
                *out_value = t;
            }
        }
        return;
    }

    // ------------------------- GEMM blocks --------------------------------
    const int wm = warp >> 2;            // 0..3 : 32-row band
    const int wn = warp & 3;             // 0..3 : 64-col band
    const int jt = blockIdx.x & 15;
    const int mg = blockIdx.x >> 4;      // 0..9
    const int j0 = jt * 128;
    const int m0 = mg * 5;

    float* s_b2  = (float*)(smem + OFF_B2);
    float* s_w3  = (float*)(smem + OFF_W3);
    float* s_red = (float*)(smem + OFF_RED);
    const uint32_t sb = smem_u32(smem);

    // ---- fills ----
    {
        const uint4* src = (const uint4*)d_B16;
        uint4* dst = (uint4*)(smem + OFF_B);
        #pragma unroll
        for (int i = 0; i < 17; i++) {
            const int idx = tid + i * 512;
            if (idx < 8448) dst[idx] = src[idx];
        }
        const uint4* srcp = (const uint4*)((const char*)d_Pj16 + (size_t)j0 * ROWB);
        uint4* dstp = (uint4*)(smem + OFF_PJ);
        #pragma unroll
        for (int i = 0; i < 9; i++) {
            const int idx = tid + i * 512;
            if (idx < 4224) dstp[idx] = srcp[idx];
        }
        if (tid < 165)
            ((uint4*)(smem + OFF_PM))[tid] =
                ((const uint4*)((const char*)d_Pm16 + (size_t)m0 * ROWB))[tid];
        if (tid < 256) s_b2[tid] = ab2[tid];
        else           s_w3[tid - 256] = aW3[tid - 256];
    }
    __syncthreads();

    // ---- per-lane ldmatrix base addresses ----
    const uint32_t aBase = sb + OFF_PJ
        + (uint32_t)(wm * 32 + (lane & 15)) * ROWB + ((lane >> 4) << 4);
    uint32_t bBase[4];
    #pragma unroll
    for (int ntp = 0; ntp < 4; ntp++)
        bBase[ntp] = sb + OFF_B
            + (uint32_t)(wn * 64 + ntp * 16 + ((lane >> 4) << 3) + (lane & 7)) * ROWB
            + (((lane >> 3) & 1) << 4);

    const int r4 = lane >> 2;
    const int kq = (lane & 3) * 2;
    const float bias3 = ab3[0];

    for (int mi = 0; mi < 5; mi++) {
        const int m = m0 + mi;
        float acc[2][8][4];
        #pragma unroll
        for (int mt = 0; mt < 2; mt++)
            #pragma unroll
            for (int nt = 0; nt < 8; nt++)
                #pragma unroll
                for (int c = 0; c < 4; c++) acc[mt][nt][c] = 0.f;

        const uint32_t pmBase = sb + OFF_PM + mi * ROWB + kq * 2;

        #pragma unroll 4
        for (int ks = 0; ks < 16; ks++) {
            const uint32_t kB = ks * 32;
            uint32_t pm0, pm1;
            asm volatile("ld.shared.b32 %0, [%1];" : "=r"(pm0) : "r"(pmBase + kB));
            asm volatile("ld.shared.b32 %0, [%1];" : "=r"(pm1) : "r"(pmBase + kB + 16));

            uint32_t a[2][4];
            #pragma unroll
            for (int mt = 0; mt < 2; mt++) {
                ldm_x4(a[mt][0], a[mt][1], a[mt][2], a[mt][3],
                       aBase + mt * (16 * ROWB) + kB);
                a[mt][0] = addrelu2(a[mt][0], pm0);
                a[mt][1] = addrelu2(a[mt][1], pm0);
                a[mt][2] = addrelu2(a[mt][2], pm1);
                a[mt][3] = addrelu2(a[mt][3], pm1);
            }
            #pragma unroll
            for (int ntp = 0; ntp < 4; ntp++) {
                uint32_t b0, b1, b2, b3;
                ldm_x4(b0, b1, b2, b3, bBase[ntp] + kB);
                HMMA(acc[0][ntp * 2],     a[0][0], a[0][1], a[0][2], a[0][3], b0, b1);
                HMMA(acc[0][ntp * 2 + 1], a[0][0], a[0][1], a[0][2], a[0][3], b2, b3);
                HMMA(acc[1][ntp * 2],     a[1][0], a[1][1], a[1][2], a[1][3], b0, b1);
                HMMA(acc[1][ntp * 2 + 1], a[1][0], a[1][1], a[1][2], a[1][3], b2, b3);
            }
        }

        // ---- fused epilogue for machine m ----
        float part[2][2] = {{0.f, 0.f}, {0.f, 0.f}};
        #pragma unroll
        for (int nt = 0; nt < 8; nt++) {
            const int col0 = wn * 64 + nt * 8 + kq;
            const float b2a = s_b2[col0],     w3a = s_w3[col0];
            const float b2b = s_b2[col0 + 1], w3b = s_w3[col0 + 1];
            #pragma unroll
            for (int mt = 0; mt < 2; mt++) {
                part[mt][0] += relu(acc[mt][nt][0] + b2a) * w3a
                             + relu(acc[mt][nt][1] + b2b) * w3b;
                part[mt][1] += relu(acc[mt][nt][2] + b2a) * w3a
                             + relu(acc[mt][nt][3] + b2b) * w3b;
            }
        }
        #pragma unroll
        for (int mt = 0; mt < 2; mt++)
            #pragma unroll
            for (int g = 0; g < 2; g++) {
                part[mt][g] += __shfl_xor_sync(0xffffffffu, part[mt][g], 1);
                part[mt][g] += __shfl_xor_sync(0xffffffffu, part[mt][g], 2);
            }
        if ((lane & 3) == 0) {
            #pragma unroll
            for (int mt = 0; mt < 2; mt++)
                #pragma unroll
                for (int g = 0; g < 2; g++) {
                    const int rl = wm * 32 + mt * 16 + g * 8 + r4;
                    s_red[rl * 4 + wn] = part[mt][g];
                }
        }
        __syncthreads();
        if (tid < 128) {
            const int j = j0 + tid;
            if (j < NJ)
                out[j * NM + m] = s_red[tid * 4 + 0] + s_red[tid * 4 + 1]
                                + s_red[tid * 4 + 2] + s_red[tid * 4 + 3] + bias3;
        }
        __syncthreads();
    }
}

// ===========================================================================
extern "C" void kernel_launch(void* const* d_in, const int* in_sizes, int n_in,
                              void* d_out, int out_size)
{
    const float* job_emb     = (const float*)d_in[0];
    const float* machine_emb = (const float*)d_in[1];
    const float* setup_emb   = (const float*)d_in[2];
    const float* gf          = (const float*)d_in[3];
    const float* Wg          = (const float*)d_in[4];
    const float* bg          = (const float*)d_in[5];
    const float* aW1         = (const float*)d_in[6];
    const float* ab1         = (const float*)d_in[7];
    const float* aW2         = (const float*)d_in[8];
    const float* ab2         = (const float*)d_in[9];
    const float* aW3         = (const float*)d_in[10];
    const float* ab3         = (const float*)d_in[11];
    const float* cW1         = (const float*)d_in[12];
    const float* cb1         = (const float*)d_in[13];
    const float* cW2         = (const float*)d_in[14];
    const float* cb2         = (const float*)d_in[15];
    const float* cW3         = (const float*)d_in[16];
    const float* cb3         = (const float*)d_in[17];

    float* out = (float*)d_out;
    float* out_value = out + (out_size - 1);

    cudaFuncSetAttribute(k3_mma, cudaFuncAttributeMaxDynamicSharedMemorySize, K3_SMEM);

    k_pre<<<601, 256>>>(job_emb, machine_emb, setup_emb, aW1, aW2);
    k_cvec<<<8, 256>>>(gf, Wg, bg, aW1, ab1);
    k_mach<<<13, 256>>>(machine_emb, aW1);
    k3_mma<<<161, 512, K3_SMEM>>>(ab2, aW3, ab3, gf, Wg, bg,
                                  cW1, cb1, cW2, cb2, cW3, cb3,
                                  out, out_value);
}

// round 6
// speedup vs baseline: 13.0756x; 1.3481x over previous
#include <cuda_runtime.h>
#include <cuda_fp16.h>
#include <cstdint>

#define H   128
#define MH  256
#define NJ  2000
#define NJP 2048
#define NM  50
#define NS  200
#define G   8

#define PADK  264                 // padded row length (halves)
#define ROWB  528                 // bytes per padded row
#define NPAIR (16 * NM)           // 800 (j-tile, machine) pairs

// ---------------- device scratch ----------------
__device__ __half d_Pj16[NJP * PADK];   // job projections, fp16
__device__ __half d_Pm16[NM * PADK];    // machine proj + cvec, fp16
__device__ __half d_B16[MH * PADK];     // aW2^T [n][k] fp16
__device__ float  d_partJ[32 * H];
__device__ float  d_partM[H];
__device__ float  d_partS[4 * H];

__device__ __forceinline__ float relu(float x) { return fmaxf(x, 0.f); }

// ===========================================================================
// k_pre: 601 blocks x 256 threads.
//   bx <  500 : job projection (4 rows)  -> d_Pj16
//   500..563  : aW2 transpose 32x32 tile -> d_B16
//   564..600  : partial column sums      -> d_partJ / d_partM / d_partS
// ===========================================================================
__global__ __launch_bounds__(256)
void k_pre(const float* __restrict__ job_emb,
           const float* __restrict__ machine_emb,
           const float* __restrict__ setup_emb,
           const float* __restrict__ aW1,
           const float* __restrict__ aW2)
{
    __shared__ float buf[32 * 33];
    const int bx = blockIdx.x;
    const int tid = threadIdx.x;

    if (bx < 500) {
        float (*s_src)[H] = (float(*)[H])buf;
        const int r0 = bx * 4;
        for (int e = tid; e < 4 * H; e += 256) {
            const int j = e >> 7, k = e & 127;
            s_src[j][k] = job_emb[(r0 + j) * H + k];
        }
        __syncthreads();
        const int col = tid;
        float a0 = 0.f, a1 = 0.f, a2 = 0.f, a3 = 0.f;
        #pragma unroll 8
        for (int k = 0; k < H; k++) {
            const float w = aW1[k * MH + col];
            a0 += s_src[0][k] * w;
            a1 += s_src[1][k] * w;
            a2 += s_src[2][k] * w;
            a3 += s_src[3][k] * w;
        }
        d_Pj16[(r0 + 0) * PADK + col] = __float2half_rn(a0);
        d_Pj16[(r0 + 1) * PADK + col] = __float2half_rn(a1);
        d_Pj16[(r0 + 2) * PADK + col] = __float2half_rn(a2);
        d_Pj16[(r0 + 3) * PADK + col] = __float2half_rn(a3);
    } else if (bx < 564) {
        float (*tt)[33] = (float(*)[33])buf;
        const int t = bx - 500;
        const int k0 = (t >> 3) * 32, n0 = (t & 7) * 32;
        const int r = tid >> 5, c = tid & 31;
        #pragma unroll
        for (int i = 0; i < 4; i++)
            tt[r + i * 8][c] = aW2[(k0 + r + i * 8) * MH + n0 + c];
        __syncthreads();
        #pragma unroll
        for (int i = 0; i < 4; i++)
            d_B16[(n0 + r + i * 8) * PADK + k0 + c] = __float2half_rn(tt[c][r + i * 8]);
    } else {
        if (tid >= 128) return;
        const int col = tid;
        const int pb = bx - 564;
        float s0 = 0.f, s1 = 0.f, s2 = 0.f, s3 = 0.f;
        if (pb < 32) {
            int r = pb;
            for (; r + 96 < NJ; r += 128) {
                s0 += job_emb[r * H + col];
                s1 += job_emb[(r + 32) * H + col];
                s2 += job_emb[(r + 64) * H + col];
                s3 += job_emb[(r + 96) * H + col];
            }
            for (; r < NJ; r += 32) s0 += job_emb[r * H + col];
            d_partJ[pb * H + col] = s0 + s1 + s2 + s3;
        } else if (pb == 32) {
            int r = 0;
            for (; r + 3 < NM; r += 4) {
                s0 += machine_emb[r * H + col];
                s1 += machine_emb[(r + 1) * H + col];
                s2 += machine_emb[(r + 2) * H + col];
                s3 += machine_emb[(r + 3) * H + col];
            }
            for (; r < NM; r++) s0 += machine_emb[r * H + col];
            d_partM[col] = s0 + s1 + s2 + s3;
        } else {
            const int sb = pb - 33;
            int r = sb;
            for (; r + 12 < NS; r += 16) {
                s0 += setup_emb[r * H + col];
                s1 += setup_emb[(r + 4) * H + col];
                s2 += setup_emb[(r + 8) * H + col];
                s3 += setup_emb[(r + 12) * H + col];
            }
            for (; r < NS; r += 4) s0 += setup_emb[r * H + col];
            d_partS[sb * H + col] = s0 + s1 + s2 + s3;
        }
    }
}

// ===========================================================================
// k_machcvec: 13 blocks x 256. Each block recomputes c_vec (cheap, redundant)
// then projects its 4 machine rows -> d_Pm16 fp16.
// ===========================================================================
__global__ __launch_bounds__(256)
void k_machcvec(const float* __restrict__ machine_emb,
                const float* __restrict__ gf,
                const float* __restrict__ Wg,
                const float* __restrict__ bg,
                const float* __restrict__ aW1,
                const float* __restrict__ ab1)
{
    __shared__ float s_sa[128], s_ge[128];
    __shared__ float s_src[4][H];
    const int tid = threadIdx.x;
    const int r0 = blockIdx.x * 4;

    if (tid < 128) {
        s_sa[tid] = (d_partS[tid] + d_partS[128 + tid] + d_partS[256 + tid]
                     + d_partS[384 + tid]) * (1.0f / NS);
    } else {
        const int c = tid - 128;
        float a = bg[c];
        #pragma unroll
        for (int g = 0; g < G; g++) a += gf[g] * Wg[g * H + c];
        s_ge[c] = relu(a);
    }
    for (int e = tid; e < 4 * H; e += 256) {
        const int j = e >> 7, k = e & 127;
        const int r = r0 + j;
        s_src[j][k] = (r < NM) ? machine_emb[r * H + k] : 0.f;
    }
    __syncthreads();

    const int col = tid;
    // c_vec[col]
    float cv = ab1[col];
    #pragma unroll 8
    for (int k = 0; k < 128; k++) {
        cv += s_sa[k] * aW1[(2 * H + k) * MH + col];
        cv += s_ge[k] * aW1[(3 * H + k) * MH + col];
    }
    // machine projections
    const float* __restrict__ W = aW1 + H * MH;
    float a0 = 0.f, a1 = 0.f, a2 = 0.f, a3 = 0.f;
    #pragma unroll 8
    for (int k = 0; k < H; k++) {
        const float w = W[k * MH + col];
        a0 += s_src[0][k] * w;
        a1 += s_src[1][k] * w;
        a2 += s_src[2][k] * w;
        a3 += s_src[3][k] * w;
    }
    if (r0 + 0 < NM) d_Pm16[(r0 + 0) * PADK + col] = __float2half_rn(a0 + cv);
    if (r0 + 1 < NM) d_Pm16[(r0 + 1) * PADK + col] = __float2half_rn(a1 + cv);
    if (r0 + 2 < NM) d_Pm16[(r0 + 2) * PADK + col] = __float2half_rn(a2 + cv);
    if (r0 + 3 < NM) d_Pm16[(r0 + 3) * PADK + col] = __float2half_rn(a3 + cv);
}

// ===========================================================================
// k3: 148 persistent blocks, single wave. Block b handles a contiguous range
// of (j-tile, machine) pairs; block 0 additionally runs the critic.
// ===========================================================================
#define OFF_B   0
#define OFF_PJ  135168
#define OFF_PM  202752      // 512B machine row
#define OFF_B2  203776
#define OFF_W3  204800
#define OFF_RED 205824
#define K3_SMEM 207872

__device__ __forceinline__ uint32_t smem_u32(const void* p) {
    uint32_t a;
    asm("{ .reg .u64 t; cvta.to.shared.u64 t, %1; cvt.u32.u64 %0, t; }" : "=r"(a) : "l"(p));
    return a;
}
__device__ __forceinline__ void ldm_x4(uint32_t& r0, uint32_t& r1, uint32_t& r2,
                                       uint32_t& r3, uint32_t addr) {
    asm volatile("ldmatrix.sync.aligned.m8n8.x4.shared.b16 {%0,%1,%2,%3}, [%4];"
                 : "=r"(r0), "=r"(r1), "=r"(r2), "=r"(r3) : "r"(addr));
}
__device__ __forceinline__ uint32_t addrelu2(uint32_t a, uint32_t pm) {
    const __half2 z = __float2half2_rn(0.f);
    __half2 x = __hadd2(*(__half2*)&a, *(__half2*)&pm);
    x = __hmax2(x, z);
    return *(uint32_t*)&x;
}
#define HMMA(acc, A0, A1, A2, A3, B0, B1)                                   \
    asm volatile(                                                            \
        "mma.sync.aligned.m16n8k16.row.col.f32.f16.f16.f32 "                \
        "{%0,%1,%2,%3}, {%4,%5,%6,%7}, {%8,%9}, {%0,%1,%2,%3};"             \
        : "+f"(acc[0]), "+f"(acc[1]), "+f"(acc[2]), "+f"(acc[3])            \
        : "r"(A0), "r"(A1), "r"(A2), "r"(A3), "r"(B0), "r"(B1))

__global__ __launch_bounds__(512, 1)
void k3_mma(const float* __restrict__ ab2,
            const float* __restrict__ aW3,
            const float* __restrict__ ab3,
            const float* __restrict__ gf,
            const float* __restrict__ Wg,
            const float* __restrict__ bg,
            const float* __restrict__ cW1, const float* __restrict__ cb1,
            const float* __restrict__ cW2, const float* __restrict__ cb2,
            const float* __restrict__ cW3, const float* __restrict__ cb3,
            float* __restrict__ out, float* __restrict__ out_value)
{
    extern __shared__ char smem[];
    const int tid  = threadIdx.x;
    const int lane = tid & 31;
    const int warp = tid >> 5;
    const int b    = blockIdx.x;

    // ---- critic (block 0 only, before GEMM; uses low smem, refilled later) --
    if (b == 0) {
        float* cs = (float*)smem;
        if (tid < 128) {
            float t = 0.f;
            #pragma unroll
            for (int g = 0; g < 32; g++) t += d_partJ[g * H + tid];
            cs[tid] = t * (1.0f / NJ);
            cs[H + tid] = d_partM[tid] * (1.0f / NM);
            cs[2 * H + tid] = (d_partS[tid] + d_partS[128 + tid] + d_partS[256 + tid]
                               + d_partS[384 + tid]) * (1.0f / NS);
            float a = bg[tid];
            #pragma unroll
            for (int g = 0; g < G; g++) a += gf[g] * Wg[g * H + tid];
            cs[3 * H + tid] = relu(a);
        }
        __syncthreads();
        {
            const int col = tid >> 1, half = tid & 1;
            float s = 0.f;
            const int kb = half * 256;
            #pragma unroll 16
            for (int k = 0; k < 256; k++)
                s += cs[kb + k] * cW1[(kb + k) * MH + col];
            s += __shfl_xor_sync(0xffffffffu, s, 1);
            __syncthreads();
            if (half == 0) cs[512 + col] = relu(s + cb1[col]);
        }
        __syncthreads();
        {
            const int col = tid >> 1, half = tid & 1;
            float s = 0.f;
            const int kb = half * 128;
            #pragma unroll 16
            for (int k = 0; k < 128; k++)
                s += cs[512 + kb + k] * cW2[(kb + k) * MH + col];
            s += __shfl_xor_sync(0xffffffffu, s, 1);
            __syncthreads();
            if (half == 0) cs[768 + col] = relu(s + cb2[col]) * cW3[col];
        }
        __syncthreads();
        {
            float v = (tid < 256) ? cs[768 + tid] : 0.f;
            #pragma unroll
            for (int off = 16; off; off >>= 1) v += __shfl_xor_sync(0xffffffffu, v, off);
            __syncthreads();
            if (lane == 0) cs[warp] = v;
            __syncthreads();
            if (tid == 0) {
                float t = cb3[0];
                #pragma unroll
                for (int w = 0; w < 16; w++) t += cs[w];
                *out_value = t;
            }
        }
        __syncthreads();
    }

    // ---- pair range for this block ----
    int p0, p1;
    if (b == 0) { p0 = 0; p1 = 3; }
    else {
        p0 = 3 + (int)(((long long)(b - 1) * 797) / 147);
        p1 = 3 + (int)(((long long)b * 797) / 147);
    }

    float* s_b2  = (float*)(smem + OFF_B2);
    float* s_w3  = (float*)(smem + OFF_W3);
    float* s_red = (float*)(smem + OFF_RED);
    const uint32_t sb = smem_u32(smem);

    // ---- fill B (once) + constants ----
    {
        const uint4* src = (const uint4*)d_B16;
        uint4* dst = (uint4*)(smem + OFF_B);
        #pragma unroll
        for (int i = 0; i < 17; i++) {
            const int idx = tid + i * 512;
            if (idx < 8448) dst[idx] = src[idx];
        }
        if (tid < 256) s_b2[tid] = ab2[tid];
        else           s_w3[tid - 256] = aW3[tid - 256];
    }

    const int wm = warp >> 2;
    const int wn = warp & 3;
    const int r4 = lane >> 2;
    const int kq = (lane & 3) * 2;
    const float bias3 = ab3[0];

    const uint32_t aBase = sb + OFF_PJ
        + (uint32_t)(wm * 32 + (lane & 15)) * ROWB + ((lane >> 4) << 4);
    uint32_t bBase[4];
    #pragma unroll
    for (int ntp = 0; ntp < 4; ntp++)
        bBase[ntp] = sb + OFF_B
            + (uint32_t)(wn * 64 + ntp * 16 + ((lane >> 4) << 3) + (lane & 7)) * ROWB
            + (((lane >> 3) & 1) << 4);
    const uint32_t pmBase = sb + OFF_PM + kq * 2;

    int cur_jt = -1;
    for (int p = p0; p < p1; p++) {
        const int jt = p / NM;
        const int m  = p - jt * NM;
        const int j0 = jt * 128;

        __syncthreads();
        if (jt != cur_jt) {
            const uint4* srcp = (const uint4*)((const char*)d_Pj16 + (size_t)j0 * ROWB);
            uint4* dstp = (uint4*)(smem + OFF_PJ);
            #pragma unroll
            for (int i = 0; i < 9; i++) {
                const int idx = tid + i * 512;
                if (idx < 4224) dstp[idx] = srcp[idx];
            }
            cur_jt = jt;
        }
        if (tid < 128)
            ((uint32_t*)(smem + OFF_PM))[tid] =
                ((const uint32_t*)((const char*)d_Pm16 + (size_t)m * ROWB))[tid];
        __syncthreads();

        float acc[2][8][4];
        #pragma unroll
        for (int mt = 0; mt < 2; mt++)
            #pragma unroll
            for (int nt = 0; nt < 8; nt++)
                #pragma unroll
                for (int c = 0; c < 4; c++) acc[mt][nt][c] = 0.f;

        #pragma unroll 4
        for (int ks = 0; ks < 16; ks++) {
            const uint32_t kB = ks * 32;
            uint32_t pm0, pm1;
            asm volatile("ld.shared.b32 %0, [%1];" : "=r"(pm0) : "r"(pmBase + kB));
            asm volatile("ld.shared.b32 %0, [%1];" : "=r"(pm1) : "r"(pmBase + kB + 16));

            uint32_t a[2][4];
            #pragma unroll
            for (int mt = 0; mt < 2; mt++) {
                ldm_x4(a[mt][0], a[mt][1], a[mt][2], a[mt][3],
                       aBase + mt * (16 * ROWB) + kB);
                a[mt][0] = addrelu2(a[mt][0], pm0);
                a[mt][1] = addrelu2(a[mt][1], pm0);
                a[mt][2] = addrelu2(a[mt][2], pm1);
                a[mt][3] = addrelu2(a[mt][3], pm1);
            }
            #pragma unroll
            for (int ntp = 0; ntp < 4; ntp++) {
                uint32_t b0, b1, b2, b3;
                ldm_x4(b0, b1, b2, b3, bBase[ntp] + kB);
                HMMA(acc[0][ntp * 2],     a[0][0], a[0][1], a[0][2], a[0][3], b0, b1);
                HMMA(acc[0][ntp * 2 + 1], a[0][0], a[0][1], a[0][2], a[0][3], b2, b3);
                HMMA(acc[1][ntp * 2],     a[1][0], a[1][1], a[1][2], a[1][3], b0, b1);
                HMMA(acc[1][ntp * 2 + 1], a[1][0], a[1][1], a[1][2], a[1][3], b2, b3);
            }
        }

        // ---- fused epilogue ----
        float part[2][2] = {{0.f, 0.f}, {0.f, 0.f}};
        #pragma unroll
        for (int nt = 0; nt < 8; nt++) {
            const int col0 = wn * 64 + nt * 8 + kq;
            const float b2a = s_b2[col0],     w3a = s_w3[col0];
            const float b2b = s_b2[col0 + 1], w3b = s_w3[col0 + 1];
            #pragma unroll
            for (int mt = 0; mt < 2; mt++) {
                part[mt][0] += relu(acc[mt][nt][0] + b2a) * w3a
                             + relu(acc[mt][nt][1] + b2b) * w3b;
                part[mt][1] += relu(acc[mt][nt][2] + b2a) * w3a
                             + relu(acc[mt][nt][3] + b2b) * w3b;
            }
        }
        #pragma unroll
        for (int mt = 0; mt < 2; mt++)
            #pragma unroll
            for (int g = 0; g < 2; g++) {
                part[mt][g] += __shfl_xor_sync(0xffffffffu, part[mt][g], 1);
                part[mt][g] += __shfl_xor_sync(0xffffffffu, part[mt][g], 2);
            }
        if ((lane & 3) == 0) {
            #pragma unroll
            for (int mt = 0; mt < 2; mt++)
                #pragma unroll
                for (int g = 0; g < 2; g++) {
                    const int rl = wm * 32 + mt * 16 + g * 8 + r4;
                    s_red[rl * 4 + wn] = part[mt][g];
                }
        }
        __syncthreads();
        if (tid < 128) {
            const int j = j0 + tid;
            if (j < NJ)
                out[j * NM + m] = s_red[tid * 4 + 0] + s_red[tid * 4 + 1]
                                + s_red[tid * 4 + 2] + s_red[tid * 4 + 3] + bias3;
        }
    }
}

// ===========================================================================
extern "C" void kernel_launch(void* const* d_in, const int* in_sizes, int n_in,
                              void* d_out, int out_size)
{
    const float* job_emb     = (const float*)d_in[0];
    const float* machine_emb = (const float*)d_in[1];
    const float* setup_emb   = (const float*)d_in[2];
    const float* gf          = (const float*)d_in[3];
    const float* Wg          = (const float*)d_in[4];
    const float* bg          = (const float*)d_in[5];
    const float* aW1         = (const float*)d_in[6];
    const float* ab1         = (const float*)d_in[7];
    const float* aW2         = (const float*)d_in[8];
    const float* ab2         = (const float*)d_in[9];
    const float* aW3         = (const float*)d_in[10];
    const float* ab3         = (const float*)d_in[11];
    const float* cW1         = (const float*)d_in[12];
    const float* cb1         = (const float*)d_in[13];
    const float* cW2         = (const float*)d_in[14];
    const float* cb2         = (const float*)d_in[15];
    const float* cW3         = (const float*)d_in[16];
    const float* cb3         = (const float*)d_in[17];

    float* out = (float*)d_out;
    float* out_value = out + (out_size - 1);

    cudaFuncSetAttribute(k3_mma, cudaFuncAttributeMaxDynamicSharedMemorySize, K3_SMEM);

    k_pre<<<601, 256>>>(job_emb, machine_emb, setup_emb, aW1, aW2);
    k_machcvec<<<13, 256>>>(machine_emb, gf, Wg, bg, aW1, ab1);
    k3_mma<<<148, 512, K3_SMEM>>>(ab2, aW3, ab3, gf, Wg, bg,
                                  cW1, cb1, cW2, cb2, cW3, cb3,
                                  out, out_value);
}